// round 2
// baseline (speedup 1.0000x reference)
#include <cuda_runtime.h>

#define C_S 384
#define C_Z 128
#define MAX_N 2048

// scratch for per-row projections (allocation-free rule: device globals)
__device__ float g_si[MAX_N];
__device__ float g_sj[MAX_N];

// ---------------------------------------------------------------------------
// Kernel 1: si[n] = dot(s[n,:], W[0:384]), sj[n] = dot(s[n,:], W[384:768])
// One warp per row n. s is tiny (1.5 MB) — this kernel is noise (~2 us).
// ---------------------------------------------------------------------------
__global__ void precompute_sisj_kernel(const float* __restrict__ s,
                                       const float* __restrict__ W,
                                       int N) {
    int warp = (blockIdx.x * blockDim.x + threadIdx.x) >> 5;
    int lane = threadIdx.x & 31;
    if (warp >= N) return;
    const float* srow = s + (size_t)warp * C_S;
    float ai = 0.f, aj = 0.f;
#pragma unroll
    for (int k = lane; k < C_S; k += 32) {
        float v = __ldg(srow + k);
        ai += v * __ldg(W + k);
        aj += v * __ldg(W + C_S + k);
    }
#pragma unroll
    for (int off = 16; off; off >>= 1) {
        ai += __shfl_xor_sync(0xFFFFFFFFu, ai, off);
        aj += __shfl_xor_sync(0xFFFFFFFFu, aj, off);
    }
    if (lane == 0) {
        g_si[warp] = ai;
        g_sj[warp] = aj;
    }
}

// ---------------------------------------------------------------------------
// Kernel 2: out[n*N + m] = g_si[n] + g_sj[m] + dot(z[n,m,:], Wz) + b
// Warp handles 16 consecutive m (same n). Each lane loads one float4 of each
// 512-byte z-row -> fully coalesced; 16 independent LDG.128 in flight per
// warp (two pipelined batches of 8 to bound register pressure). z is
// read-once so loads use evict-first (__ldcs); out uses streaming store.
// ---------------------------------------------------------------------------
#define ROWS_PER_WARP 16

__global__ __launch_bounds__(256) void contact_main_kernel(
    const float* __restrict__ z,
    const float* __restrict__ W,
    const float* __restrict__ bias,
    float* __restrict__ out,
    int N) {
    int warp = (blockIdx.x * blockDim.x + threadIdx.x) >> 5;
    int lane = threadIdx.x & 31;

    long long base = (long long)warp * ROWS_PER_WARP;
    long long total = (long long)N * (long long)N;
    if (base >= total) return;

    int n  = (int)(base / N);
    int m0 = (int)(base - (long long)n * N);   // N % 16 == 0 -> all 16 share n

    // Wz = W[768:896], resident in L1/L2 after first touch
    const float4* wz4 = (const float4*)(W + 2 * C_S);
    float4 wz = __ldg(wz4 + lane);
    float b0  = __ldg(bias);

    const float4* z4 = (const float4*)z;
    size_t row0 = ((size_t)n * N + m0) * (C_Z / 4);  // float4 index of row m0

    float acc[ROWS_PER_WARP];

    // Batch A: rows 0..7 (8 independent loads in flight)
    float4 va[8];
#pragma unroll
    for (int i = 0; i < 8; i++)
        va[i] = __ldcs(z4 + row0 + (size_t)i * (C_Z / 4) + lane);
    // Batch B: rows 8..15 issued before consuming A (up to 16 in flight)
    float4 vb[8];
#pragma unroll
    for (int i = 0; i < 8; i++)
        vb[i] = __ldcs(z4 + row0 + (size_t)(8 + i) * (C_Z / 4) + lane);

#pragma unroll
    for (int i = 0; i < 8; i++)
        acc[i] = va[i].x * wz.x + va[i].y * wz.y + va[i].z * wz.z + va[i].w * wz.w;
#pragma unroll
    for (int i = 0; i < 8; i++)
        acc[8 + i] = vb[i].x * wz.x + vb[i].y * wz.y + vb[i].z * wz.z + vb[i].w * wz.w;

#pragma unroll
    for (int off = 16; off; off >>= 1) {
#pragma unroll
        for (int i = 0; i < ROWS_PER_WARP; i++)
            acc[i] += __shfl_xor_sync(0xFFFFFFFFu, acc[i], off);
    }

    if (lane == 0) {
        float sn = g_si[n] + b0;
        float4* o4 = (float4*)(out + base);
#pragma unroll
        for (int q = 0; q < ROWS_PER_WARP / 4; q++) {
            float4 r;
            r.x = acc[q * 4 + 0] + sn + g_sj[m0 + q * 4 + 0];
            r.y = acc[q * 4 + 1] + sn + g_sj[m0 + q * 4 + 1];
            r.z = acc[q * 4 + 2] + sn + g_sj[m0 + q * 4 + 2];
            r.w = acc[q * 4 + 3] + sn + g_sj[m0 + q * 4 + 3];
            __stcs(o4 + q, r);
        }
    }
}

extern "C" void kernel_launch(void* const* d_in, const int* in_sizes, int n_in,
                              void* d_out, int out_size) {
    const float* s    = (const float*)d_in[0];   // (1, N, 384)
    const float* z    = (const float*)d_in[1];   // (1, N, N, 128)
    const float* W    = (const float*)d_in[2];   // (1, 896)
    const float* bias = (const float*)d_in[3];   // (1,)
    float* out = (float*)d_out;                  // (1, N, N, 1)

    int N = in_sizes[0] / C_S;                   // B=1

    // Kernel 1: one warp per row, 256 threads/block
    {
        int warps = N;
        int threads = 256;
        int blocks = (warps * 32 + threads - 1) / threads;
        precompute_sisj_kernel<<<blocks, threads>>>(s, W, N);
    }

    // Kernel 2: one warp per 16 outputs
    {
        long long total = (long long)N * (long long)N;
        long long warps = (total + ROWS_PER_WARP - 1) / ROWS_PER_WARP;
        int threads = 256;
        long long blocks = (warps * 32 + threads - 1) / threads;
        contact_main_kernel<<<(unsigned)blocks, threads>>>(z, W, bias, out, N);
    }
}

// round 4
// speedup vs baseline: 1.2251x; 1.2251x over previous
#include <cuda_runtime.h>

#define C_S 384
#define C_Z 128
#define MAX_N 2048

// scratch for per-row projections (allocation-free rule: device globals)
__device__ float g_si[MAX_N];
__device__ float g_sj[MAX_N];

// ---------------------------------------------------------------------------
// Kernel 1: si[n] = dot(s[n,:], W[0:384]), sj[n] = dot(s[n,:], W[384:768])
// One warp per row n. s is tiny (1.5 MB) — this kernel is noise (~2 us).
// ---------------------------------------------------------------------------
__global__ void precompute_sisj_kernel(const float* __restrict__ s,
                                       const float* __restrict__ W,
                                       int N) {
    int warp = (blockIdx.x * blockDim.x + threadIdx.x) >> 5;
    int lane = threadIdx.x & 31;
    if (warp >= N) return;
    const float* srow = s + (size_t)warp * C_S;
    float ai = 0.f, aj = 0.f;
#pragma unroll
    for (int k = lane; k < C_S; k += 32) {
        float v = __ldg(srow + k);
        ai += v * __ldg(W + k);
        aj += v * __ldg(W + C_S + k);
    }
#pragma unroll
    for (int off = 16; off; off >>= 1) {
        ai += __shfl_xor_sync(0xFFFFFFFFu, ai, off);
        aj += __shfl_xor_sync(0xFFFFFFFFu, aj, off);
    }
    if (lane == 0) {
        g_si[warp] = ai;
        g_sj[warp] = aj;
    }
}

// ---------------------------------------------------------------------------
// Kernel 2: out[n*N + m] = g_si[n] + g_sj[m] + dot(z[n,m,:], Wz) + b
// Warp handles 8 consecutive m (same n). Each lane loads one float4 of the
// 512-byte z-row -> fully coalesced, MLP=8 LDG.128 per warp.
// Reduction: select-and-exchange — 8 accumulators reduced with 9 shfls
// (instead of a 40-shfl butterfly). After the merge, lane l holds the
// complete sum for row (l & 7); lanes 0..7 do a coalesced 32B store.
// ---------------------------------------------------------------------------
__global__ __launch_bounds__(256) void contact_main_kernel(
    const float* __restrict__ z,
    const float* __restrict__ W,
    const float* __restrict__ bias,
    float* __restrict__ out,
    int N) {
    int warp = (blockIdx.x * blockDim.x + threadIdx.x) >> 5;
    int lane = threadIdx.x & 31;

    long long base = (long long)warp * 8;
    long long total = (long long)N * (long long)N;
    if (base >= total) return;

    int n  = (int)(base / N);
    int m0 = (int)(base - (long long)n * N);   // N % 8 == 0 -> all 8 share n

    // Wz = W[768:896], resident in L1/L2 after first touch
    const float4* wz4 = (const float4*)(W + 2 * C_S);
    float4 wz = __ldg(wz4 + lane);
    float b0  = __ldg(bias);

    const float4* z4 = (const float4*)z;
    size_t row0 = ((size_t)n * N + m0) * (C_Z / 4);  // float4 index of row m0

    float a0, a1, a2, a3, a4, a5, a6, a7;
    {
        float4 v0 = __ldg(z4 + row0 + 0 * (C_Z / 4) + lane);
        float4 v1 = __ldg(z4 + row0 + 1 * (C_Z / 4) + lane);
        float4 v2 = __ldg(z4 + row0 + 2 * (C_Z / 4) + lane);
        float4 v3 = __ldg(z4 + row0 + 3 * (C_Z / 4) + lane);
        float4 v4 = __ldg(z4 + row0 + 4 * (C_Z / 4) + lane);
        float4 v5 = __ldg(z4 + row0 + 5 * (C_Z / 4) + lane);
        float4 v6 = __ldg(z4 + row0 + 6 * (C_Z / 4) + lane);
        float4 v7 = __ldg(z4 + row0 + 7 * (C_Z / 4) + lane);
        a0 = v0.x * wz.x + v0.y * wz.y + v0.z * wz.z + v0.w * wz.w;
        a1 = v1.x * wz.x + v1.y * wz.y + v1.z * wz.z + v1.w * wz.w;
        a2 = v2.x * wz.x + v2.y * wz.y + v2.z * wz.z + v2.w * wz.w;
        a3 = v3.x * wz.x + v3.y * wz.y + v3.z * wz.z + v3.w * wz.w;
        a4 = v4.x * wz.x + v4.y * wz.y + v4.z * wz.z + v4.w * wz.w;
        a5 = v5.x * wz.x + v5.y * wz.y + v5.z * wz.z + v5.w * wz.w;
        a6 = v6.x * wz.x + v6.y * wz.y + v6.z * wz.z + v6.w * wz.w;
        a7 = v7.x * wz.x + v7.y * wz.y + v7.z * wz.z + v7.w * wz.w;
    }

    // Select-and-exchange multi-value reduction.
    // Stage 1 (bit 0): merge (a0,a1) (a2,a3) (a4,a5) (a6,a7)
    bool s0b = (lane & 1);
    float t0 = s0b ? a1 : a0;
    float t1 = s0b ? a3 : a2;
    float t2 = s0b ? a5 : a4;
    float t3 = s0b ? a7 : a6;
    t0 += __shfl_xor_sync(0xFFFFFFFFu, s0b ? a0 : a1, 1);
    t1 += __shfl_xor_sync(0xFFFFFFFFu, s0b ? a2 : a3, 1);
    t2 += __shfl_xor_sync(0xFFFFFFFFu, s0b ? a4 : a5, 1);
    t3 += __shfl_xor_sync(0xFFFFFFFFu, s0b ? a6 : a7, 1);
    // Stage 2 (bit 1): merge (t0,t1) (t2,t3)
    bool s1b = (lane & 2);
    float u0 = s1b ? t1 : t0;
    float u1 = s1b ? t3 : t2;
    u0 += __shfl_xor_sync(0xFFFFFFFFu, s1b ? t0 : t1, 2);
    u1 += __shfl_xor_sync(0xFFFFFFFFu, s1b ? t2 : t3, 2);
    // Stage 3 (bit 2): merge (u0,u1)
    bool s2b = (lane & 4);
    float r = s2b ? u1 : u0;
    r += __shfl_xor_sync(0xFFFFFFFFu, s2b ? u0 : u1, 4);
    // Final butterfly across xor-groups of 8
    r += __shfl_xor_sync(0xFFFFFFFFu, r, 8);
    r += __shfl_xor_sync(0xFFFFFFFFu, r, 16);
    // lane l now holds the full 32-lane sum for row index (l & 7)

    if (lane < 8) {
        float sn = g_si[n] + b0;
        out[base + lane] = r + sn + g_sj[m0 + lane];
    }
}

extern "C" void kernel_launch(void* const* d_in, const int* in_sizes, int n_in,
                              void* d_out, int out_size) {
    const float* s    = (const float*)d_in[0];   // (1, N, 384)
    const float* z    = (const float*)d_in[1];   // (1, N, N, 128)
    const float* W    = (const float*)d_in[2];   // (1, 896)
    const float* bias = (const float*)d_in[3];   // (1,)
    float* out = (float*)d_out;                  // (1, N, N, 1)

    int N = in_sizes[0] / C_S;                   // B=1

    // Kernel 1: one warp per row, 256 threads/block
    {
        int warps = N;
        int threads = 256;
        int blocks = (warps * 32 + threads - 1) / threads;
        precompute_sisj_kernel<<<blocks, threads>>>(s, W, N);
    }

    // Kernel 2: one warp per 8 outputs
    {
        long long total = (long long)N * (long long)N;
        long long warps = (total + 7) / 8;
        int threads = 256;
        long long blocks = (warps * 32 + threads - 1) / threads;
        contact_main_kernel<<<(unsigned)blocks, threads>>>(z, W, bias, out, N);
    }
}